// round 7
// baseline (speedup 1.0000x reference)
#include <cuda_runtime.h>
#include <cuda_bf16.h>

#define BATCH 8192
#define TLEN  512
#define NIN   8
#define NH    16

typedef unsigned long long u64;

__device__ __forceinline__ u64 pack2(float lo, float hi) {
    u64 r; asm("mov.b64 %0, {%1, %2};" : "=l"(r) : "f"(lo), "f"(hi)); return r;
}
__device__ __forceinline__ void unpack2(u64 v, float& lo, float& hi) {
    asm("mov.b64 {%0, %1}, %2;" : "=f"(lo), "=f"(hi) : "l"(v));
}
__device__ __forceinline__ u64 fma2(u64 a, u64 b, u64 c) {
    u64 d; asm("fma.rn.f32x2 %0, %1, %2, %3;" : "=l"(d) : "l"(a), "l"(b), "l"(c)); return d;
}
__device__ __forceinline__ u64 mul2(u64 a, u64 b) {
    u64 d; asm("mul.rn.f32x2 %0, %1, %2;" : "=l"(d) : "l"(a), "l"(b)); return d;
}
__device__ __forceinline__ u64 add2(u64 a, u64 b) {
    u64 d; asm("add.rn.f32x2 %0, %1, %2;" : "=l"(d) : "l"(a), "l"(b)); return d;
}
__device__ __forceinline__ float tanh_hw(float a) {
    float r; asm("tanh.approx.f32 %0, %1;" : "=f"(r) : "f"(a)); return r;
}

// 4 lanes per GROUP; each group processes TWO batch elements (ILP=2, weights
// shared in registers). Lane g owns hidden rows 4g..4g+3; rotated local pair
// indexing keeps both reduce-scatter rounds SEL-free. 16384 threads =
// 512 warps = 128 CTAs x 128thr -> exactly 1 warp per SMSP (uniform),
// two independent step-chains per warp fill each other's stall bubbles.
__global__ __launch_bounds__(128) void rnn_scan_kernel(
    const float* __restrict__ x,     // [B, T, 8]
    const float* __restrict__ W_ih,  // [16, 8]
    const float* __restrict__ W_hh,  // [16, 16]
    const float* __restrict__ b_ih,  // [16]
    const float* __restrict__ b_hh,  // [16]
    const float* __restrict__ fc_w,  // [1, 16]
    const float* __restrict__ fc_b,  // [1]
    float* __restrict__ out)         // [B, 1]
{
    const int tid = blockIdx.x * blockDim.x + threadIdx.x;
    const int grp = tid >> 2;           // 4096 groups
    const int g   = tid & 3;
    const int src2 = (g + 3) & 3;       // round-2 source lane (g-1 mod 4)
    const int bA = 2 * grp;
    const int bB = 2 * grp + 1;

    // ---- rotated packed weight slices (shared by both batches) ----
    u64 whh2[8][4], wih2[8][2];
#pragma unroll
    for (int i = 0; i < 8; i++) {
        const int rA = (4 * g + 2 * i) & 15;
        const int rB = rA + 1;
#pragma unroll
        for (int r = 0; r < 4; r++)
            whh2[i][r] = pack2(W_hh[rA * NH + 4 * g + r], W_hh[rB * NH + 4 * g + r]);
#pragma unroll
        for (int c = 0; c < 2; c++)
            wih2[i][c] = pack2(W_ih[rA * NIN + 2 * g + c], W_ih[rB * NIN + 2 * g + c]);
    }
    u64 bias2[2];
#pragma unroll
    for (int i = 0; i < 2; i++)
        bias2[i] = pack2(b_ih[4*g + 2*i]     + b_hh[4*g + 2*i],
                         b_ih[4*g + 2*i + 1] + b_hh[4*g + 2*i + 1]);
    float fcw[4];
#pragma unroll
    for (int r = 0; r < 4; r++) fcw[r] = fc_w[4*g + r];
    const float fcb = fc_b[0];

    // state per batch: dup pairs {h,h} + scalars
    u64 hd[2][4];
    float hs[2][4];
#pragma unroll
    for (int u = 0; u < 2; u++)
#pragma unroll
        for (int r = 0; r < 4; r++) { hd[u][r] = 0ull; hs[u][r] = 0.f; }

    const float* xlaneA = x + (size_t)bA * (TLEN * NIN) + 2 * g;
    const float* xlaneB = x + (size_t)bB * (TLEN * NIN) + 2 * g;

    // 2-step-deep prefetch for both batches
    float2 xbufA0 = *(const float2*)(xlaneA);
    float2 xbufA1 = *(const float2*)(xlaneA + NIN);
    float2 xbufB0 = *(const float2*)(xlaneB);
    float2 xbufB1 = *(const float2*)(xlaneB + NIN);

#define RNN_STEP2(XA, XB)                                                       \
    {                                                                           \
        u64 xd[2][2];                                                           \
        xd[0][0] = pack2((XA).x, (XA).x); xd[0][1] = pack2((XA).y, (XA).y);     \
        xd[1][0] = pack2((XB).x, (XB).x); xd[1][1] = pack2((XB).y, (XB).y);     \
        u64 acc[2][8];                                                          \
        _Pragma("unroll")                                                       \
        for (int i = 0; i < 8; i++) {                                           \
            _Pragma("unroll")                                                   \
            for (int u = 0; u < 2; u++) {                                       \
                u64 a = mul2(wih2[i][0], xd[u][0]);                             \
                a = fma2(wih2[i][1], xd[u][1], a);                              \
                a = fma2(whh2[i][0], hd[u][0], a);                              \
                a = fma2(whh2[i][1], hd[u][1], a);                              \
                a = fma2(whh2[i][2], hd[u][2], a);                              \
                a = fma2(whh2[i][3], hd[u][3], a);                              \
                acc[u][i] = a;                                                  \
            }                                                                   \
        }                                                                       \
        /* round 1: uniform xor-2 exchange */                                   \
        u64 b1[2][4];                                                           \
        _Pragma("unroll")                                                       \
        for (int i = 0; i < 4; i++) {                                           \
            _Pragma("unroll")                                                   \
            for (int u = 0; u < 2; u++) {                                       \
                u64 r = __shfl_xor_sync(0xffffffffu, acc[u][4 + i], 2, 4);      \
                b1[u][i] = add2(acc[u][i], r);                                  \
            }                                                                   \
        }                                                                       \
        /* round 2: uniform idx shfl from lane g-1; bias pre-add in shadow */   \
        u64 c2[2][2];                                                           \
        _Pragma("unroll")                                                       \
        for (int i = 0; i < 2; i++) {                                           \
            _Pragma("unroll")                                                   \
            for (int u = 0; u < 2; u++) {                                       \
                u64 r = __shfl_sync(0xffffffffu, b1[u][2 + i], src2, 4);        \
                u64 t = add2(b1[u][i], bias2[i]);                               \
                c2[u][i] = add2(t, r);                                          \
            }                                                                   \
        }                                                                       \
        _Pragma("unroll")                                                       \
        for (int u = 0; u < 2; u++) {                                           \
            float a0, a1, a2, a3;                                               \
            unpack2(c2[u][0], a0, a1);                                          \
            unpack2(c2[u][1], a2, a3);                                          \
            hs[u][0] = tanh_hw(a0); hs[u][1] = tanh_hw(a1);                     \
            hs[u][2] = tanh_hw(a2); hs[u][3] = tanh_hw(a3);                     \
            hd[u][0] = pack2(hs[u][0], hs[u][0]);                               \
            hd[u][1] = pack2(hs[u][1], hs[u][1]);                               \
            hd[u][2] = pack2(hs[u][2], hs[u][2]);                               \
            hd[u][3] = pack2(hs[u][3], hs[u][3]);                               \
        }                                                                       \
    }

    for (int t = 0; t < TLEN; t += 2) {
        float2 cA0 = xbufA0, cB0 = xbufB0;
        if (t + 2 < TLEN) {
            xbufA0 = *(const float2*)(xlaneA + (size_t)(t + 2) * NIN);
            xbufB0 = *(const float2*)(xlaneB + (size_t)(t + 2) * NIN);
        }
        RNN_STEP2(cA0, cB0);
        float2 cA1 = xbufA1, cB1 = xbufB1;
        if (t + 3 < TLEN) {
            xbufA1 = *(const float2*)(xlaneA + (size_t)(t + 3) * NIN);
            xbufB1 = *(const float2*)(xlaneB + (size_t)(t + 3) * NIN);
        }
        RNN_STEP2(cA1, cB1);
    }
#undef RNN_STEP2

    // ---- final projection for both batches ----
#pragma unroll
    for (int u = 0; u < 2; u++) {
        float p = hs[u][0] * fcw[0];
        p = fmaf(hs[u][1], fcw[1], p);
        p = fmaf(hs[u][2], fcw[2], p);
        p = fmaf(hs[u][3], fcw[3], p);
        p += __shfl_xor_sync(0xffffffffu, p, 1, 4);
        p += __shfl_xor_sync(0xffffffffu, p, 2, 4);
        if (g == 0) out[2 * grp + u] = p + fcb;
    }
}

extern "C" void kernel_launch(void* const* d_in, const int* in_sizes, int n_in,
                              void* d_out, int out_size) {
    const float* x    = (const float*)d_in[0];
    const float* W_ih = (const float*)d_in[1];
    const float* W_hh = (const float*)d_in[2];
    const float* b_ih = (const float*)d_in[3];
    const float* b_hh = (const float*)d_in[4];
    const float* fc_w = (const float*)d_in[5];
    const float* fc_b = (const float*)d_in[6];
    float* out = (float*)d_out;

    const int threads = 128;
    const int blocks  = (BATCH / 2 * 4) / threads;  // 128 CTAs, 16384 threads
    rnn_scan_kernel<<<blocks, threads>>>(x, W_ih, W_hh, b_ih, b_hh, fc_w, fc_b, out);
}

// round 8
// speedup vs baseline: 1.3622x; 1.3622x over previous
#include <cuda_runtime.h>
#include <cuda_bf16.h>

#define BATCH 8192
#define TLEN  512
#define NIN   8
#define NH    16

typedef unsigned long long u64;

__device__ __forceinline__ u64 pack2(float lo, float hi) {
    u64 r; asm("mov.b64 %0, {%1, %2};" : "=l"(r) : "f"(lo), "f"(hi)); return r;
}
__device__ __forceinline__ void unpack2(u64 v, float& lo, float& hi) {
    asm("mov.b64 {%0, %1}, %2;" : "=f"(lo), "=f"(hi) : "l"(v));
}
__device__ __forceinline__ u64 fma2(u64 a, u64 b, u64 c) {
    u64 d; asm("fma.rn.f32x2 %0, %1, %2, %3;" : "=l"(d) : "l"(a), "l"(b), "l"(c)); return d;
}
__device__ __forceinline__ u64 mul2(u64 a, u64 b) {
    u64 d; asm("mul.rn.f32x2 %0, %1, %2;" : "=l"(d) : "l"(a), "l"(b)); return d;
}
__device__ __forceinline__ u64 add2(u64 a, u64 b) {
    u64 d; asm("add.rn.f32x2 %0, %1, %2;" : "=l"(d) : "l"(a), "l"(b)); return d;
}
__device__ __forceinline__ float tanh_hw(float a) {
    float r; asm("tanh.approx.f32 %0, %1;" : "=f"(r) : "f"(a)); return r;
}

// 8 lanes per batch element. Lane g in [0,8) owns row-pair {2g, 2g+1}, the
// h-slice {h[2g], h[2g+1]} and input x[g]. Rotated local indexing: local pair
// i <-> global pair (g+i)&7, making all THREE reduce-scatter rounds use
// uniform register indices:
//   r1: b1[i] = acc[i] + shfl_xor(acc[i+4], 4)          (i<4)
//   r2: b2[i] = b1[i]  + shfl(b1[2+i], g-2, w=8)        (i<2)
//   r3: c    = b2[0]   + shfl(b2[1],  g-1, w=8) + bias
// 65536 threads = 2048 warps = 3.46 warps/SMSP -> hardware latency hiding.
__global__ __launch_bounds__(128) void rnn_scan_kernel(
    const float* __restrict__ x,     // [B, T, 8]
    const float* __restrict__ W_ih,  // [16, 8]
    const float* __restrict__ W_hh,  // [16, 16]
    const float* __restrict__ b_ih,  // [16]
    const float* __restrict__ b_hh,  // [16]
    const float* __restrict__ fc_w,  // [1, 16]
    const float* __restrict__ fc_b,  // [1]
    float* __restrict__ out)         // [B, 1]
{
    const int tid = blockIdx.x * blockDim.x + threadIdx.x;
    const int b   = tid >> 3;           // batch element
    const int g   = tid & 7;            // lane within 8-wide group
    const int src2 = (g + 6) & 7;       // round-2 source (g-2 mod 8)
    const int src3 = (g + 7) & 7;       // round-3 source (g-1 mod 8)

    // ---- rotated packed weight slices ----
    // local pair i -> global pair p=(g+i)&7 -> rows 2p, 2p+1
    u64 whh2[8][2], wih2[8];
#pragma unroll
    for (int i = 0; i < 8; i++) {
        const int p  = (g + i) & 7;
        const int rA = 2 * p, rB = 2 * p + 1;
#pragma unroll
        for (int r = 0; r < 2; r++)
            whh2[i][r] = pack2(W_hh[rA * NH + 2 * g + r], W_hh[rB * NH + 2 * g + r]);
        wih2[i] = pack2(W_ih[rA * NIN + g], W_ih[rB * NIN + g]);
    }
    const u64 bias2 = pack2(b_ih[2*g]     + b_hh[2*g],
                            b_ih[2*g + 1] + b_hh[2*g + 1]);
    const float fcw0 = fc_w[2*g], fcw1 = fc_w[2*g + 1];
    const float fcb = fc_b[0];

    // own h values as dup pairs {h,h}
    u64 hd0 = 0ull, hd1 = 0ull;
    float hs0 = 0.f, hs1 = 0.f;

    const float* xlane = x + (size_t)b * (TLEN * NIN) + g;

    // 2-step x prefetch (scalar per lane)
    float xb0 = xlane[0];
    float xb1 = xlane[NIN];

#define RNN_STEP(XS)                                                            \
    {                                                                           \
        const u64 xd = pack2((XS), (XS));                                       \
        u64 acc[8];                                                             \
        _Pragma("unroll")                                                       \
        for (int i = 0; i < 8; i++) {                                           \
            u64 a = mul2(wih2[i], xd);                                          \
            a = fma2(whh2[i][0], hd0, a);                                       \
            a = fma2(whh2[i][1], hd1, a);                                       \
            acc[i] = a;                                                         \
        }                                                                       \
        /* round 1: xor-4 */                                                    \
        u64 b1[4];                                                              \
        _Pragma("unroll")                                                       \
        for (int i = 0; i < 4; i++) {                                           \
            u64 r = __shfl_xor_sync(0xffffffffu, acc[4 + i], 4, 8);             \
            b1[i] = add2(acc[i], r);                                            \
        }                                                                       \
        /* round 2: idx shfl from g-2 */                                        \
        u64 b2[2];                                                              \
        _Pragma("unroll")                                                       \
        for (int i = 0; i < 2; i++) {                                           \
            u64 r = __shfl_sync(0xffffffffu, b1[2 + i], src2, 8);               \
            b2[i] = add2(b1[i], r);                                             \
        }                                                                       \
        /* round 3: idx shfl from g-1; bias pre-added in shadow */              \
        u64 t3 = add2(b2[0], bias2);                                            \
        u64 r3 = __shfl_sync(0xffffffffu, b2[1], src3, 8);                      \
        u64 c  = add2(t3, r3);                                                  \
        float a0, a1;                                                           \
        unpack2(c, a0, a1);                                                     \
        hs0 = tanh_hw(a0); hs1 = tanh_hw(a1);                                   \
        hd0 = pack2(hs0, hs0); hd1 = pack2(hs1, hs1);                           \
    }

    for (int t = 0; t < TLEN; t += 2) {
        float c0 = xb0;
        if (t + 2 < TLEN) xb0 = xlane[(size_t)(t + 2) * NIN];
        RNN_STEP(c0);
        float c1 = xb1;
        if (t + 3 < TLEN) xb1 = xlane[(size_t)(t + 3) * NIN];
        RNN_STEP(c1);
    }
#undef RNN_STEP

    // ---- final projection: lane g holds h[2g], h[2g+1] ----
    float p = hs0 * fcw0;
    p = fmaf(hs1, fcw1, p);
    p += __shfl_xor_sync(0xffffffffu, p, 1, 8);
    p += __shfl_xor_sync(0xffffffffu, p, 2, 8);
    p += __shfl_xor_sync(0xffffffffu, p, 4, 8);
    if (g == 0) out[b] = p + fcb;
}

extern "C" void kernel_launch(void* const* d_in, const int* in_sizes, int n_in,
                              void* d_out, int out_size) {
    const float* x    = (const float*)d_in[0];
    const float* W_ih = (const float*)d_in[1];
    const float* W_hh = (const float*)d_in[2];
    const float* b_ih = (const float*)d_in[3];
    const float* b_hh = (const float*)d_in[4];
    const float* fc_w = (const float*)d_in[5];
    const float* fc_b = (const float*)d_in[6];
    float* out = (float*)d_out;

    const int threads = 128;
    const int blocks  = (BATCH * 8) / threads;  // 512 CTAs, 65536 threads
    rnn_scan_kernel<<<blocks, threads>>>(x, W_ih, W_hh, b_ih, b_hh, fc_w, fc_b, out);
}